// round 1
// baseline (speedup 1.0000x reference)
#include <cuda_runtime.h>
#include <cuda_bf16.h>
#include <cstdint>

// Problem: out[b,n] = max(0, 1 - sum_k (1 - xs[b,k]) * sigmoid(W[k,n]))
// B=4096, K=1024, N=1024, fp32 in/out.

static constexpr int Bdim = 4096;
static constexpr int Kdim = 1024;
static constexpr int Ndim = 1024;

// Scratch (allocation-free rule: __device__ globals)
__device__ __nv_bfloat16 g_A[(size_t)Bdim * Kdim];  // (1 - xs) as bf16, row-major [B,K]
__device__ __nv_bfloat16 g_W[(size_t)Kdim * Ndim];  // sigmoid(W) as bf16, row-major [K,N]

// ---------------------------------------------------------------------------
// Prep kernels: fp32 -> bf16 with the elementwise transforms fused.
// ---------------------------------------------------------------------------
__global__ void prep_A_kernel(const float* __restrict__ xs) {
    int i = blockIdx.x * blockDim.x + threadIdx.x;
    const int n4 = Bdim * Kdim / 4;
    if (i >= n4) return;
    float4 v = reinterpret_cast<const float4*>(xs)[i];
    __nv_bfloat162 lo = __floats2bfloat162_rn(1.0f - v.x, 1.0f - v.y);
    __nv_bfloat162 hi = __floats2bfloat162_rn(1.0f - v.z, 1.0f - v.w);
    reinterpret_cast<__nv_bfloat162*>(g_A)[2 * i]     = lo;
    reinterpret_cast<__nv_bfloat162*>(g_A)[2 * i + 1] = hi;
}

__global__ void prep_W_kernel(const float* __restrict__ w) {
    int i = blockIdx.x * blockDim.x + threadIdx.x;
    const int n4 = Kdim * Ndim / 4;
    if (i >= n4) return;
    float4 v = reinterpret_cast<const float4*>(w)[i];
    float s0 = 1.0f / (1.0f + __expf(-v.x));
    float s1 = 1.0f / (1.0f + __expf(-v.y));
    float s2 = 1.0f / (1.0f + __expf(-v.z));
    float s3 = 1.0f / (1.0f + __expf(-v.w));
    __nv_bfloat162 lo = __floats2bfloat162_rn(s0, s1);
    __nv_bfloat162 hi = __floats2bfloat162_rn(s2, s3);
    reinterpret_cast<__nv_bfloat162*>(g_W)[2 * i]     = lo;
    reinterpret_cast<__nv_bfloat162*>(g_W)[2 * i + 1] = hi;
}

// ---------------------------------------------------------------------------
// GEMM: C = A @ W, epilogue out = max(0, 1 - C)
// CTA tile 128x128, K-tile 32, 256 threads (8 warps, each 32(M) x 64(N)).
// cp.async double-buffered SMEM, ldmatrix + mma.sync.m16n8k16 bf16/f32.
// ---------------------------------------------------------------------------
static constexpr int BM = 128;
static constexpr int BN = 128;
static constexpr int BK = 32;
static constexpr int LDA = BK + 8;   // 40 elems = 80B rows (16B-aligned stride)
static constexpr int LDB = BN + 8;   // 136 elems = 272B rows (16B-aligned stride)

__device__ __forceinline__ uint32_t smem_u32(const void* p) {
    return (uint32_t)__cvta_generic_to_shared(p);
}

__global__ __launch_bounds__(256, 2)
void fuzzyand_gemm_kernel(float* __restrict__ out) {
    __shared__ __nv_bfloat16 As[2][BM * LDA];
    __shared__ __nv_bfloat16 Bs[2][BK * LDB];

    const int tid  = threadIdx.x;
    const int wid  = tid >> 5;
    const int lane = tid & 31;
    const int wm   = (wid & 3) * 32;   // warp M offset within CTA (4 warps along M)
    const int wn   = (wid >> 2) * 64;  // warp N offset within CTA (2 warps along N)

    const int bm = blockIdx.y * BM;
    const int bn = blockIdx.x * BN;

    const __nv_bfloat16* Ag = g_A + (size_t)bm * Kdim;
    const __nv_bfloat16* Wg = g_W + bn;

    float acc[2][8][4];
    #pragma unroll
    for (int mi = 0; mi < 2; mi++)
        #pragma unroll
        for (int ni = 0; ni < 8; ni++)
            #pragma unroll
            for (int e = 0; e < 4; e++) acc[mi][ni][e] = 0.0f;

    // --- async tile loaders: 16B per cp.async, 2 chunks/thread per tile ---
    auto load_tiles = [&](int buf, int kt) {
        const __nv_bfloat16* a_src = Ag + kt * BK;
        #pragma unroll
        for (int j = 0; j < 2; j++) {
            int c  = tid + j * 256;          // 0..511
            int r  = c >> 2;                 // 128 rows, 4 chunks/row
            int cc = (c & 3) * 8;
            uint32_t dst = smem_u32(&As[buf][r * LDA + cc]);
            const void* src = a_src + (size_t)r * Kdim + cc;
            asm volatile("cp.async.cg.shared.global [%0], [%1], 16;\n" :: "r"(dst), "l"(src));
        }
        const __nv_bfloat16* b_src = Wg + (size_t)kt * BK * Ndim;
        #pragma unroll
        for (int j = 0; j < 2; j++) {
            int c  = tid + j * 256;          // 0..511
            int r  = c >> 4;                 // 32 rows, 16 chunks/row
            int cc = (c & 15) * 8;
            uint32_t dst = smem_u32(&Bs[buf][r * LDB + cc]);
            const void* src = b_src + (size_t)r * Ndim + cc;
            asm volatile("cp.async.cg.shared.global [%0], [%1], 16;\n" :: "r"(dst), "l"(src));
        }
        asm volatile("cp.async.commit_group;\n");
    };

    load_tiles(0, 0);

    const int KT = Kdim / BK;  // 32
    for (int kt = 0; kt < KT; kt++) {
        asm volatile("cp.async.wait_group 0;\n");
        __syncthreads();
        if (kt + 1 < KT) load_tiles((kt + 1) & 1, kt + 1);

        const int buf = kt & 1;
        #pragma unroll
        for (int ks = 0; ks < 2; ks++) {
            const int k0 = ks * 16;

            // A fragments: two m16k16 tiles
            uint32_t a[2][4];
            #pragma unroll
            for (int mi = 0; mi < 2; mi++) {
                int row = wm + mi * 16 + (lane & 15);
                int col = k0 + ((lane >> 4) << 3);
                uint32_t addr = smem_u32(&As[buf][row * LDA + col]);
                asm volatile(
                    "ldmatrix.sync.aligned.m8n8.x4.shared.b16 {%0,%1,%2,%3}, [%4];\n"
                    : "=r"(a[mi][0]), "=r"(a[mi][1]), "=r"(a[mi][2]), "=r"(a[mi][3])
                    : "r"(addr));
            }

            // B fragments: four k16n16 transposed loads -> eight n8 tiles
            uint32_t b[8][2];
            #pragma unroll
            for (int nc = 0; nc < 4; nc++) {
                int krow = k0 + (lane & 15);
                int col  = wn + nc * 16 + ((lane >> 4) << 3);
                uint32_t addr = smem_u32(&Bs[buf][krow * LDB + col]);
                asm volatile(
                    "ldmatrix.sync.aligned.m8n8.x4.trans.shared.b16 {%0,%1,%2,%3}, [%4];\n"
                    : "=r"(b[2 * nc][0]), "=r"(b[2 * nc][1]),
                      "=r"(b[2 * nc + 1][0]), "=r"(b[2 * nc + 1][1])
                    : "r"(addr));
            }

            #pragma unroll
            for (int mi = 0; mi < 2; mi++)
                #pragma unroll
                for (int ni = 0; ni < 8; ni++) {
                    asm volatile(
                        "mma.sync.aligned.m16n8k16.row.col.f32.bf16.bf16.f32 "
                        "{%0,%1,%2,%3}, {%4,%5,%6,%7}, {%8,%9}, {%0,%1,%2,%3};\n"
                        : "+f"(acc[mi][ni][0]), "+f"(acc[mi][ni][1]),
                          "+f"(acc[mi][ni][2]), "+f"(acc[mi][ni][3])
                        : "r"(a[mi][0]), "r"(a[mi][1]), "r"(a[mi][2]), "r"(a[mi][3]),
                          "r"(b[ni][0]), "r"(b[ni][1]));
                }
        }
        __syncthreads();
    }

    // --- epilogue: out = max(0, 1 - acc), float2 stores ---
    float* outp = out + (size_t)bm * Ndim + bn;
    #pragma unroll
    for (int mi = 0; mi < 2; mi++) {
        #pragma unroll
        for (int ni = 0; ni < 8; ni++) {
            int r0 = wm + mi * 16 + (lane >> 2);
            int c0 = wn + ni * 8 + (lane & 3) * 2;
            float2 v0, v1;
            v0.x = fmaxf(0.0f, 1.0f - acc[mi][ni][0]);
            v0.y = fmaxf(0.0f, 1.0f - acc[mi][ni][1]);
            v1.x = fmaxf(0.0f, 1.0f - acc[mi][ni][2]);
            v1.y = fmaxf(0.0f, 1.0f - acc[mi][ni][3]);
            *reinterpret_cast<float2*>(&outp[(size_t)r0 * Ndim + c0])       = v0;
            *reinterpret_cast<float2*>(&outp[(size_t)(r0 + 8) * Ndim + c0]) = v1;
        }
    }
}

// ---------------------------------------------------------------------------
extern "C" void kernel_launch(void* const* d_in, const int* in_sizes, int n_in,
                              void* d_out, int out_size) {
    const float* xs = (const float*)d_in[0];   // [4096, 1024] fp32
    const float* w  = (const float*)d_in[1];   // [1024, 1024] fp32
    float* out = (float*)d_out;                // [4096, 1024] fp32

    (void)in_sizes; (void)n_in; (void)out_size;

    prep_A_kernel<<<(Bdim * Kdim / 4 + 255) / 256, 256>>>(xs);
    prep_W_kernel<<<(Kdim * Ndim / 4 + 255) / 256, 256>>>(w);

    dim3 grid(Ndim / BN, Bdim / BM);  // (8, 32) = 256 CTAs
    fuzzyand_gemm_kernel<<<grid, 256>>>(out);
}

// round 3
// speedup vs baseline: 1.2452x; 1.2452x over previous
#include <cuda_runtime.h>
#include <cuda_bf16.h>
#include <cstdint>

// out[b,n] = max(0, 1 - sum_k (1 - xs[b,k]) * sigmoid(W[k,n]))
// B=4096, K=1024, N=1024, fp32 in/out.
static constexpr int Bdim = 4096;
static constexpr int Kdim = 1024;
static constexpr int Ndim = 1024;

// Tiled, pre-swizzled operand storage (__device__ globals: allocation-free rule).
// g_A: blocks (mt, kt), mt=0..31, kt=0..15. Block = 128 rows x 64 k (bf16),
//      128B rows, SW128 swizzled, 16KB contiguous. offset = (mt*16+kt)*16384.
// g_W: blocks (nt, kt), nt=0..7, kt=0..15. Block = two halves (n 0..63, 64..127),
//      each 64 k-rows x 64 n (bf16) = 128B rows, SW128 swizzled, 8KB per half.
__device__ __align__(128) __nv_bfloat16 g_A[(size_t)Bdim * Kdim];
__device__ __align__(128) __nv_bfloat16 g_W[(size_t)Kdim * Ndim];

__device__ __host__ __forceinline__ uint32_t swz(uint32_t x) {
    return x ^ ((x >> 3) & 0x70);
}

// ---------------------------------------------------------------------------
// Fused prep: blocks [0,512) -> A (1-x, bf16, tiled+swizzled)
//             blocks [512,640) -> W (sigmoid, bf16, tiled+swizzled)
// Each thread: 4 x 16B chunks (8 bf16 each) for MLP.
// ---------------------------------------------------------------------------
__global__ void prep_kernel(const float* __restrict__ xs, const float* __restrict__ w) {
    const int tid = threadIdx.x;
    char* gA = reinterpret_cast<char*>(g_A);
    char* gW = reinterpret_cast<char*>(g_W);

    if (blockIdx.x < 512) {
        int base = blockIdx.x * 256 + tid;
#pragma unroll
        for (int j = 0; j < 4; j++) {
            int c = base + j * 131072;          // chunk id, 512K total
            int b = c >> 7, k8 = c & 127;       // row b, 8-elem group k8
            const float4* s = reinterpret_cast<const float4*>(xs + (size_t)b * 1024 + k8 * 8);
            float4 v0 = s[0], v1 = s[1];
            __nv_bfloat162 p0 = __floats2bfloat162_rn(1.0f - v0.x, 1.0f - v0.y);
            __nv_bfloat162 p1 = __floats2bfloat162_rn(1.0f - v0.z, 1.0f - v0.w);
            __nv_bfloat162 p2 = __floats2bfloat162_rn(1.0f - v1.x, 1.0f - v1.y);
            __nv_bfloat162 p3 = __floats2bfloat162_rn(1.0f - v1.z, 1.0f - v1.w);
            uint4 u;
            u.x = *reinterpret_cast<uint32_t*>(&p0);
            u.y = *reinterpret_cast<uint32_t*>(&p1);
            u.z = *reinterpret_cast<uint32_t*>(&p2);
            u.w = *reinterpret_cast<uint32_t*>(&p3);
            int kt = k8 >> 3, c8 = k8 & 7, mt = b >> 7, r = b & 127;
            size_t off = (size_t)(mt * 16 + kt) * 16384 + swz(r * 128 + c8 * 16);
            *reinterpret_cast<uint4*>(gA + off) = u;
        }
    } else {
        int base = (blockIdx.x - 512) * 256 + tid;
#pragma unroll
        for (int j = 0; j < 4; j++) {
            int c = base + j * 32768;           // chunk id, 128K total
            int k = c >> 7, n8 = c & 127;
            const float4* s = reinterpret_cast<const float4*>(w + (size_t)k * 1024 + n8 * 8);
            float4 v0 = s[0], v1 = s[1];
            float s0 = 1.0f / (1.0f + __expf(-v0.x));
            float s1 = 1.0f / (1.0f + __expf(-v0.y));
            float s2 = 1.0f / (1.0f + __expf(-v0.z));
            float s3 = 1.0f / (1.0f + __expf(-v0.w));
            float s4 = 1.0f / (1.0f + __expf(-v1.x));
            float s5 = 1.0f / (1.0f + __expf(-v1.y));
            float s6 = 1.0f / (1.0f + __expf(-v1.z));
            float s7 = 1.0f / (1.0f + __expf(-v1.w));
            __nv_bfloat162 p0 = __floats2bfloat162_rn(s0, s1);
            __nv_bfloat162 p1 = __floats2bfloat162_rn(s2, s3);
            __nv_bfloat162 p2 = __floats2bfloat162_rn(s4, s5);
            __nv_bfloat162 p3 = __floats2bfloat162_rn(s6, s7);
            uint4 u;
            u.x = *reinterpret_cast<uint32_t*>(&p0);
            u.y = *reinterpret_cast<uint32_t*>(&p1);
            u.z = *reinterpret_cast<uint32_t*>(&p2);
            u.w = *reinterpret_cast<uint32_t*>(&p3);
            int nt = n8 >> 4, h = (n8 >> 3) & 1, nl8 = n8 & 7;
            int kt = k >> 6, kl = k & 63;
            size_t off = (size_t)(nt * 16 + kt) * 16384 + h * 8192 +
                         swz(kl * 128 + nl8 * 16);
            *reinterpret_cast<uint4*>(gW + off) = u;
        }
    }
}

// ---------------------------------------------------------------------------
// GEMM: 128x128 CTA tile, BK=64, 3-stage cp.async.bulk pipeline,
// ldmatrix + mma.sync.m16n8k16, one __syncthreads per K-tile.
// ---------------------------------------------------------------------------
static constexpr int STAGES = 3;
static constexpr int KT = Kdim / 64;                 // 16
static constexpr uint32_t STAGE_B = 32768;           // 16KB A + 16KB B
static constexpr uint32_t BUF_OFF = 128;
static constexpr uint32_t SMEM_BYTES = BUF_OFF + STAGES * STAGE_B;  // 98432

__device__ __forceinline__ void mbar_wait(uint32_t addr, uint32_t parity) {
    asm volatile(
        "{\n\t.reg .pred P;\n"
        "W_%=:\n\t"
        "mbarrier.try_wait.parity.acquire.cta.shared::cta.b64 P, [%0], %1, 0x989680;\n\t"
        "@P bra.uni D_%=;\n\t"
        "bra.uni W_%=;\n"
        "D_%=:\n\t}"
        :: "r"(addr), "r"(parity) : "memory");
}

__global__ __launch_bounds__(256, 2) void fuzzyand_gemm(float* __restrict__ out) {
    extern __shared__ char smem[];
    const uint32_t sb = (uint32_t)__cvta_generic_to_shared(smem);
    const int tid = threadIdx.x;
    const int wid = tid >> 5;
    const int lane = tid & 31;
    const int wm = (wid & 3) * 32;
    const int wn = (wid >> 2) * 64;
    const int bm = blockIdx.y * 128;
    const int bn = blockIdx.x * 128;

    if (tid == 0) {
#pragma unroll
        for (int s = 0; s < STAGES; s++)
            asm volatile("mbarrier.init.shared.b64 [%0], %1;"
                         :: "r"(sb + 8 * s), "r"(1u) : "memory");
    }
    __syncthreads();

    const char* Ab = reinterpret_cast<const char*>(g_A) + (size_t)(blockIdx.y * 16) * 16384;
    const char* Bb = reinterpret_cast<const char*>(g_W) + (size_t)(blockIdx.x * 16) * 16384;

    auto issue = [&](int stage, int kt) {
        uint32_t mb = sb + 8 * stage;
        uint32_t dst = sb + BUF_OFF + stage * STAGE_B;
        asm volatile("mbarrier.arrive.expect_tx.shared.b64 _, [%0], %1;"
                     :: "r"(mb), "r"(STAGE_B) : "memory");
        asm volatile(
            "cp.async.bulk.shared::cluster.global.mbarrier::complete_tx::bytes "
            "[%0], [%1], %2, [%3];"
            :: "r"(dst), "l"(Ab + (size_t)kt * 16384), "r"(16384u), "r"(mb) : "memory");
        asm volatile(
            "cp.async.bulk.shared::cluster.global.mbarrier::complete_tx::bytes "
            "[%0], [%1], %2, [%3];"
            :: "r"(dst + 16384u), "l"(Bb + (size_t)kt * 16384), "r"(16384u), "r"(mb) : "memory");
    };

    if (tid == 0) { issue(0, 0); issue(1, 1); }

    float acc[2][8][4];
#pragma unroll
    for (int mi = 0; mi < 2; mi++)
#pragma unroll
        for (int ni = 0; ni < 8; ni++)
#pragma unroll
            for (int e = 0; e < 4; e++) acc[mi][ni][e] = 0.0f;

    // precomputed swizzled row bases (bytecol < 128 never carries into bits>=7)
    const uint32_t a_row0 = (uint32_t)(wm + (lane & 15)) * 128;
    const uint32_t a_xor0 = ((wm + (lane & 15)) & 7) << 4;
    const uint32_t a_row1 = (uint32_t)(wm + 16 + (lane & 15)) * 128;
    const uint32_t a_xor1 = ((wm + 16 + (lane & 15)) & 7) << 4;
    const uint32_t a_hi = (lane >> 4) << 4;     // +16B for second k8 group
    const uint32_t b_half = (uint32_t)((wn >> 6) * 8192);
    const uint32_t b_nb = (uint32_t)((wn & 63) * 2 + ((lane >> 4) << 4));

#pragma unroll 1
    for (int kt = 0; kt < KT; kt++) {
        const int stage = kt % STAGES;
        mbar_wait(sb + 8 * stage, (uint32_t)((kt / STAGES) & 1));

        const uint32_t a_s = sb + BUF_OFF + stage * STAGE_B;
        const uint32_t b_s = a_s + 16384;

#pragma unroll
        for (int ks = 0; ks < 4; ks++) {
            const uint32_t kb = ks * 32;

            uint32_t a[2][4];
            {
                uint32_t bc = kb + a_hi;
                uint32_t ad0 = a_s + ((a_row0 + bc) ^ a_xor0);
                uint32_t ad1 = a_s + ((a_row1 + bc) ^ a_xor1);
                asm volatile(
                    "ldmatrix.sync.aligned.m8n8.x4.shared.b16 {%0,%1,%2,%3}, [%4];"
                    : "=r"(a[0][0]), "=r"(a[0][1]), "=r"(a[0][2]), "=r"(a[0][3])
                    : "r"(ad0));
                asm volatile(
                    "ldmatrix.sync.aligned.m8n8.x4.shared.b16 {%0,%1,%2,%3}, [%4];"
                    : "=r"(a[1][0]), "=r"(a[1][1]), "=r"(a[1][2]), "=r"(a[1][3])
                    : "r"(ad1));
            }

            uint32_t b[8][2];
            {
                uint32_t krow = (uint32_t)(ks * 16 + (lane & 15));
                uint32_t base = krow * 128;
                uint32_t kxor = (krow & 7) << 4;
#pragma unroll
                for (int nc = 0; nc < 4; nc++) {
                    uint32_t bc = b_nb + nc * 32;
                    uint32_t ad = b_s + b_half + ((base + bc) ^ kxor);
                    asm volatile(
                        "ldmatrix.sync.aligned.m8n8.x4.trans.shared.b16 {%0,%1,%2,%3}, [%4];"
                        : "=r"(b[2 * nc][0]), "=r"(b[2 * nc][1]),
                          "=r"(b[2 * nc + 1][0]), "=r"(b[2 * nc + 1][1])
                        : "r"(ad));
                }
            }

#pragma unroll
            for (int mi = 0; mi < 2; mi++)
#pragma unroll
                for (int ni = 0; ni < 8; ni++) {
                    asm volatile(
                        "mma.sync.aligned.m16n8k16.row.col.f32.bf16.bf16.f32 "
                        "{%0,%1,%2,%3}, {%4,%5,%6,%7}, {%8,%9}, {%0,%1,%2,%3};"
                        : "+f"(acc[mi][ni][0]), "+f"(acc[mi][ni][1]),
                          "+f"(acc[mi][ni][2]), "+f"(acc[mi][ni][3])
                        : "r"(a[mi][0]), "r"(a[mi][1]), "r"(a[mi][2]), "r"(a[mi][3]),
                          "r"(b[ni][0]), "r"(b[ni][1]));
                }
        }

        __syncthreads();   // all warps done reading this stage (and stage kt-1)
        if (tid == 0 && kt + 2 < KT) issue((kt + 2) % STAGES, kt + 2);
    }

    // Epilogue: out = max(0, 1 - acc), float2 stores straight from fragments.
    float* outp = out + (size_t)bm * Ndim + bn;
#pragma unroll
    for (int mi = 0; mi < 2; mi++) {
#pragma unroll
        for (int ni = 0; ni < 8; ni++) {
            int r0 = wm + mi * 16 + (lane >> 2);
            int c0 = wn + ni * 8 + (lane & 3) * 2;
            float2 v0, v1;
            v0.x = fmaxf(0.0f, 1.0f - acc[mi][ni][0]);
            v0.y = fmaxf(0.0f, 1.0f - acc[mi][ni][1]);
            v1.x = fmaxf(0.0f, 1.0f - acc[mi][ni][2]);
            v1.y = fmaxf(0.0f, 1.0f - acc[mi][ni][3]);
            *reinterpret_cast<float2*>(&outp[(size_t)r0 * Ndim + c0])       = v0;
            *reinterpret_cast<float2*>(&outp[(size_t)(r0 + 8) * Ndim + c0]) = v1;
        }
    }
}

// ---------------------------------------------------------------------------
extern "C" void kernel_launch(void* const* d_in, const int* in_sizes, int n_in,
                              void* d_out, int out_size) {
    const float* xs = (const float*)d_in[0];   // [4096,1024] fp32
    const float* w  = (const float*)d_in[1];   // [1024,1024] fp32
    float* out = (float*)d_out;
    (void)in_sizes; (void)n_in; (void)out_size;

    prep_kernel<<<640, 256>>>(xs, w);

    cudaFuncSetAttribute(fuzzyand_gemm,
                         cudaFuncAttributeMaxDynamicSharedMemorySize, SMEM_BYTES);
    dim3 grid(Ndim / 128, Bdim / 128);  // (8, 32) = 256 CTAs
    fuzzyand_gemm<<<grid, 256, SMEM_BYTES>>>(out);
}